// round 2
// baseline (speedup 1.0000x reference)
#include <cuda_runtime.h>
#include <cstdint>

// Problem constants
#define B_WIN   4096
#define SEQ     64
#define CDIM    256
#define NHEAD   8
#define HDIM    32
#define NWIN    64
#define MAX_LOGIT 4.6051701859880913680f  // log(100)

// ---------------- scratch (device globals; no runtime allocation) ----------
__device__ float g_qkv[(size_t)B_WIN * SEQ * 3 * CDIM];   // [b*64+n][768], col = s*256 + h*32 + d
__device__ float g_attn[(size_t)B_WIN * SEQ * CDIM];      // [b*64+n][256], col = h*32 + d

// ---------------- GEMM: C[M x N] = A[M x K] * B[N x K]^T + bias[N] ---------
#define BM 128
#define BN 64
#define BK 16
#define TM 8
#define TN 4
// 256 threads: 16 x 16 thread grid, each thread 8x4 outputs.

__global__ __launch_bounds__(256) void gemm_nt_bias(
    const float* __restrict__ A, const float* __restrict__ B,
    const float* __restrict__ bias, float* __restrict__ C,
    int M, int Nn, int K)
{
    __shared__ float As[BK][BM + 8];   // transposed A tile, padded
    __shared__ float Bs[BK][BN + 8];   // transposed B tile, padded

    const int tid = threadIdx.x;
    const int block_m = blockIdx.y * BM;
    const int block_n = blockIdx.x * BN;

    const int tm = (tid >> 4) * TM;    // 0..120
    const int tn = (tid & 15) * TN;    // 0..60

    float acc[TM][TN];
    #pragma unroll
    for (int i = 0; i < TM; i++)
        #pragma unroll
        for (int j = 0; j < TN; j++) acc[i][j] = 0.f;

    for (int k0 = 0; k0 < K; k0 += BK) {
        // Load A tile: 128x16 = 512 float4 slots, 2 per thread
        #pragma unroll
        for (int i = 0; i < 2; i++) {
            int s  = tid * 2 + i;
            int r  = s >> 2;
            int c4 = (s & 3) * 4;
            float4 va = *reinterpret_cast<const float4*>(
                A + (size_t)(block_m + r) * K + k0 + c4);
            As[c4 + 0][r] = va.x;
            As[c4 + 1][r] = va.y;
            As[c4 + 2][r] = va.z;
            As[c4 + 3][r] = va.w;
        }
        // Load B tile: 64x16 = 256 float4 slots, 1 per thread
        {
            int r  = tid >> 2;
            int c4 = (tid & 3) * 4;
            float4 vb = *reinterpret_cast<const float4*>(
                B + (size_t)(block_n + r) * K + k0 + c4);
            Bs[c4 + 0][r] = vb.x;
            Bs[c4 + 1][r] = vb.y;
            Bs[c4 + 2][r] = vb.z;
            Bs[c4 + 3][r] = vb.w;
        }
        __syncthreads();

        #pragma unroll
        for (int kk = 0; kk < BK; kk++) {
            float ra[TM], rb[TN];
            float4 a0 = *reinterpret_cast<float4*>(&As[kk][tm]);
            float4 a1 = *reinterpret_cast<float4*>(&As[kk][tm + 4]);
            ra[0]=a0.x; ra[1]=a0.y; ra[2]=a0.z; ra[3]=a0.w;
            ra[4]=a1.x; ra[5]=a1.y; ra[6]=a1.z; ra[7]=a1.w;
            float4 b0 = *reinterpret_cast<float4*>(&Bs[kk][tn]);
            rb[0]=b0.x; rb[1]=b0.y; rb[2]=b0.z; rb[3]=b0.w;
            #pragma unroll
            for (int i = 0; i < TM; i++)
                #pragma unroll
                for (int j = 0; j < TN; j++)
                    acc[i][j] = fmaf(ra[i], rb[j], acc[i][j]);
        }
        __syncthreads();
    }

    // Epilogue: bias + store (float4 per row)
    float bb[TN];
    #pragma unroll
    for (int j = 0; j < TN; j++) bb[j] = bias[block_n + tn + j];
    #pragma unroll
    for (int i = 0; i < TM; i++) {
        float4 o;
        o.x = acc[i][0] + bb[0];
        o.y = acc[i][1] + bb[1];
        o.z = acc[i][2] + bb[2];
        o.w = acc[i][3] + bb[3];
        *reinterpret_cast<float4*>(
            C + (size_t)(block_m + tm + i) * Nn + block_n + tn) = o;
    }
}

// ---------------- RoPE + L2 normalize (in place on q,k of g_qkv) -----------
// One warp per (b, n, s in {0,1}, h) row of 32 elements.
__global__ __launch_bounds__(256) void rope_norm_kernel()
{
    const int warps_per_block = 256 / 32;
    int wg   = blockIdx.x * warps_per_block + (threadIdx.x >> 5);
    int lane = threadIdx.x & 31;
    // decode: wg = ((b*64 + n)*2 + s)*8 + h ; total = 4096*64*2*8 = 2^22
    int h = wg & 7;
    int s = (wg >> 3) & 1;
    int n = (wg >> 4) & 63;
    int b = wg >> 10;
    if (b >= B_WIN) return;

    float* row = g_qkv + ((size_t)(b * SEQ + n)) * (3 * CDIM) + s * CDIM + h * HDIM;
    float v = row[lane];

    int i = lane & 15;
    float inv_freq = powf(10000.f, -(float)i * (1.f / 16.f));
    float t   = (float)n + 0.1f;                 // VIEW_ID * VIEW_OFFSET
    float ang = t * inv_freq;
    float c, sn;
    __sincosf(ang, &sn, &c);
    // improve accuracy: recompute with accurate sin/cos (cheap kernel)
    sn = sinf(ang); c = cosf(ang);

    float partner = __shfl_xor_sync(0xffffffffu, v, 16);
    float r = (lane < 16) ? fmaf(v, c, -partner * sn)
                          : fmaf(partner, sn, v * c);

    float ss = r * r;
    #pragma unroll
    for (int o = 16; o; o >>= 1) ss += __shfl_xor_sync(0xffffffffu, ss, o);
    float nrm = fmaxf(sqrtf(ss), 1e-12f);
    row[lane] = r / nrm;
}

// ---------------- fused attention per (b, h) block --------------------------
__global__ __launch_bounds__(256) void attn_kernel(
    const float* __restrict__ mask, const float* __restrict__ logit_scale,
    float* __restrict__ out)
{
    const int h = blockIdx.x;       // 0..7
    const int b = blockIdx.y;       // 0..4095
    const int w = b & (NWIN - 1);
    const int tid = threadIdx.x;

    __shared__ float qT[HDIM][SEQ + 8];   // [d][n]
    __shared__ float kT[HDIM][SEQ + 8];
    __shared__ float vs[SEQ][HDIM + 4];   // [n][d]
    __shared__ float S[SEQ][SEQ + 4];

    const float* base = g_qkv + (size_t)b * SEQ * (3 * CDIM) + h * HDIM;

    // Load q,k,v tiles: each 64x32 floats = 512 float4; 2 slots/thread/tensor
    #pragma unroll
    for (int i = 0; i < 2; i++) {
        int slot = tid * 2 + i;
        int n  = slot >> 3;
        int c4 = (slot & 7) * 4;
        const float* rp = base + (size_t)n * (3 * CDIM) + c4;
        float4 q4 = *reinterpret_cast<const float4*>(rp);
        float4 k4 = *reinterpret_cast<const float4*>(rp + CDIM);
        float4 v4 = *reinterpret_cast<const float4*>(rp + 2 * CDIM);
        qT[c4+0][n]=q4.x; qT[c4+1][n]=q4.y; qT[c4+2][n]=q4.z; qT[c4+3][n]=q4.w;
        kT[c4+0][n]=k4.x; kT[c4+1][n]=k4.y; kT[c4+2][n]=k4.z; kT[c4+3][n]=k4.w;
        vs[n][c4+0]=v4.x; vs[n][c4+1]=v4.y; vs[n][c4+2]=v4.z; vs[n][c4+3]=v4.w;
    }
    float scale = __expf(fminf(logit_scale[h], MAX_LOGIT));
    __syncthreads();

    // ---- S = (qn . kn) * scale + mask ----  thread tile 4x4
    {
        const int r0 = (tid >> 4) << 2;
        const int c0 = (tid & 15) << 2;
        float acc[4][4];
        #pragma unroll
        for (int i=0;i<4;i++)
            #pragma unroll
            for (int j=0;j<4;j++) acc[i][j] = 0.f;

        #pragma unroll
        for (int kk = 0; kk < HDIM; kk++) {
            float4 qv = *reinterpret_cast<float4*>(&qT[kk][r0]);
            float4 kv = *reinterpret_cast<float4*>(&kT[kk][c0]);
            float ra[4] = {qv.x, qv.y, qv.z, qv.w};
            float rb[4] = {kv.x, kv.y, kv.z, kv.w};
            #pragma unroll
            for (int i=0;i<4;i++)
                #pragma unroll
                for (int j=0;j<4;j++)
                    acc[i][j] = fmaf(ra[i], rb[j], acc[i][j]);
        }
        const float* mrow = mask + (size_t)w * SEQ * SEQ;
        #pragma unroll
        for (int i=0;i<4;i++)
            #pragma unroll
            for (int j=0;j<4;j++)
                S[r0+i][c0+j] = fmaf(acc[i][j], scale, mrow[(r0+i)*SEQ + c0+j]);
    }
    __syncthreads();

    // ---- softmax over each row; 4 threads per row ----
    {
        const int row = tid >> 2;
        const int q16 = (tid & 3) * 16;
        float mx = -1e30f;
        #pragma unroll
        for (int j = 0; j < 16; j++) mx = fmaxf(mx, S[row][q16 + j]);
        mx = fmaxf(mx, __shfl_xor_sync(0xffffffffu, mx, 1));
        mx = fmaxf(mx, __shfl_xor_sync(0xffffffffu, mx, 2));
        float e[16]; float sum = 0.f;
        #pragma unroll
        for (int j = 0; j < 16; j++) { e[j] = __expf(S[row][q16 + j] - mx); sum += e[j]; }
        sum += __shfl_xor_sync(0xffffffffu, sum, 1);
        sum += __shfl_xor_sync(0xffffffffu, sum, 2);
        float inv = __frcp_rn(sum);
        #pragma unroll
        for (int j = 0; j < 16; j++) S[row][q16 + j] = e[j] * inv;
    }
    __syncthreads();

    // ---- out = P . v ----  thread: 2 rows x 4 cols
    {
        const int r0 = (tid >> 3) << 1;
        const int d0 = (tid & 7) << 2;
        float o0[4] = {0,0,0,0}, o1[4] = {0,0,0,0};
        #pragma unroll
        for (int c = 0; c < SEQ; c++) {
            float p0 = S[r0][c];
            float p1 = S[r0 + 1][c];
            float4 vv = *reinterpret_cast<float4*>(&vs[c][d0]);
            o0[0] = fmaf(p0, vv.x, o0[0]); o0[1] = fmaf(p0, vv.y, o0[1]);
            o0[2] = fmaf(p0, vv.z, o0[2]); o0[3] = fmaf(p0, vv.w, o0[3]);
            o1[0] = fmaf(p1, vv.x, o1[0]); o1[1] = fmaf(p1, vv.y, o1[1]);
            o1[2] = fmaf(p1, vv.z, o1[2]); o1[3] = fmaf(p1, vv.w, o1[3]);
        }
        float* orow = out + ((size_t)(b * SEQ + r0)) * CDIM + h * HDIM + d0;
        *reinterpret_cast<float4*>(orow)        = make_float4(o0[0], o0[1], o0[2], o0[3]);
        *reinterpret_cast<float4*>(orow + CDIM) = make_float4(o1[0], o1[1], o1[2], o1[3]);
    }
}

// ---------------- launch ----------------------------------------------------
extern "C" void kernel_launch(void* const* d_in, const int* in_sizes, int n_in,
                              void* d_out, int out_size)
{
    const float* x           = (const float*)d_in[0];
    const float* mask        = (const float*)d_in[1];
    const float* qkv_w       = (const float*)d_in[2];
    const float* qkv_b       = (const float*)d_in[3];
    const float* proj_w      = (const float*)d_in[4];
    const float* proj_b      = (const float*)d_in[5];
    const float* logit_scale = (const float*)d_in[6];
    float* out = (float*)d_out;

    float* qkv_buf;
    float* attn_buf;
    cudaGetSymbolAddress((void**)&qkv_buf, g_qkv);
    cudaGetSymbolAddress((void**)&attn_buf, g_attn);

    const int M = B_WIN * SEQ;          // 262144

    // 1) QKV GEMM: [M,768] = x[M,256] * qkv_w[768,256]^T + qkv_b
    {
        dim3 grid(3 * CDIM / BN, M / BM);   // (12, 2048)
        gemm_nt_bias<<<grid, 256>>>(x, qkv_w, qkv_b, qkv_buf, M, 3 * CDIM, CDIM);
    }
    // 2) RoPE + L2 norm on q,k
    {
        int total_warps = B_WIN * SEQ * 2 * NHEAD;   // 2^22
        rope_norm_kernel<<<total_warps / 8, 256>>>();
    }
    // 3) fused attention
    {
        dim3 grid(NHEAD, B_WIN);
        attn_kernel<<<grid, 256>>>(mask, logit_scale, attn_buf);
    }
    // 4) proj GEMM: out[M,256] = attn[M,256] * proj_w[256,256]^T + proj_b
    {
        dim3 grid(CDIM / BN, M / BM);       // (4, 2048)
        gemm_nt_bias<<<grid, 256>>>(attn_buf, proj_w, proj_b, out, M, CDIM, CDIM);
    }
}

// round 4
// speedup vs baseline: 1.5906x; 1.5906x over previous
#include <cuda_runtime.h>
#include <cuda_bf16.h>
#include <cstdint>

// Problem constants
#define B_WIN   4096
#define SEQ     64
#define CDIM    256
#define NHEAD   8
#define HDIM    32
#define NWIN    64
#define MAX_LOGIT 4.6051701859880913680f  // log(100)

// ---------------- scratch (device globals; no runtime allocation) ----------
__device__ float g_qkv[(size_t)B_WIN * SEQ * 3 * CDIM];   // [b*64+n][768]
__device__ float g_attn[(size_t)B_WIN * SEQ * CDIM];      // [b*64+n][256]

// ================= bf16-split tensor-core GEMM =============================
// C[M x N] = A[M x K] * B[N x K]^T + bias[N], fp32 in/out, 3-pass bf16 split.
#define GBM 128
#define GBN 64
#define GBK 32
#define LDS 40            // bf16 elements per smem row (32 data + 8 pad)

__device__ __forceinline__ uint32_t pack_bf2(float a, float b) {
    __nv_bfloat162 t = __floats2bfloat162_rn(a, b);
    return *reinterpret_cast<uint32_t*>(&t);
}

__device__ __forceinline__ void ldsm_x4(uint32_t addr, uint32_t& r0, uint32_t& r1,
                                        uint32_t& r2, uint32_t& r3) {
    asm volatile("ldmatrix.sync.aligned.m8n8.x4.shared.b16 {%0,%1,%2,%3}, [%4];"
                 : "=r"(r0), "=r"(r1), "=r"(r2), "=r"(r3) : "r"(addr));
}

__device__ __forceinline__ void mma_bf16(float* c, const uint32_t* a,
                                         uint32_t b0, uint32_t b1) {
    asm volatile(
        "mma.sync.aligned.m16n8k16.row.col.f32.bf16.bf16.f32 "
        "{%0,%1,%2,%3}, {%4,%5,%6,%7}, {%8,%9}, {%0,%1,%2,%3};"
        : "+f"(c[0]), "+f"(c[1]), "+f"(c[2]), "+f"(c[3])
        : "r"(a[0]), "r"(a[1]), "r"(a[2]), "r"(a[3]), "r"(b0), "r"(b1));
}

// split float4 into hi/lo bf16x4 packed as uint2
__device__ __forceinline__ void split4(float4 v, uint2& hi, uint2& lo) {
    float vv[4] = {v.x, v.y, v.z, v.w};
    float hf[4], lf[4];
    #pragma unroll
    for (int j = 0; j < 4; j++) {
        __nv_bfloat16 h = __float2bfloat16_rn(vv[j]);
        hf[j] = __bfloat162float(h);
        lf[j] = vv[j] - hf[j];
    }
    hi.x = pack_bf2(hf[0], hf[1]); hi.y = pack_bf2(hf[2], hf[3]);
    lo.x = pack_bf2(lf[0], lf[1]); lo.y = pack_bf2(lf[2], lf[3]);
}

__global__ __launch_bounds__(256, 2) void gemm_bf16_split(
    const float* __restrict__ A, const float* __restrict__ Bw,
    const float* __restrict__ bias, float* __restrict__ C,
    int M, int N, int K)
{
    __shared__ __align__(16) __nv_bfloat16 sAh[GBM * LDS];
    __shared__ __align__(16) __nv_bfloat16 sAl[GBM * LDS];
    __shared__ __align__(16) __nv_bfloat16 sBh[GBN * LDS];
    __shared__ __align__(16) __nv_bfloat16 sBl[GBN * LDS];

    const int tid  = threadIdx.x;
    const int lane = tid & 31;
    const int wid  = tid >> 5;
    const int bm   = blockIdx.y * GBM;
    const int bn   = blockIdx.x * GBN;
    const int wm   = (wid & 3) * 32;     // warp row offset within block
    const int wn   = (wid >> 2) * 32;    // warp col offset within block

    // ---- fragment ldmatrix base addresses (lane-dependent) ----
    const int lr   = lane & 7;
    const int seg  = lane >> 3;
    const int frow = lr + (seg & 1) * 8;       // row within 16-row group
    const int fcol = (seg >> 1) * 8;           // k offset 0 or 8

    const uint32_t bAh = (uint32_t)__cvta_generic_to_shared(sAh);
    const uint32_t bAl = (uint32_t)__cvta_generic_to_shared(sAl);
    const uint32_t bBh = (uint32_t)__cvta_generic_to_shared(sBh);
    const uint32_t bBl = (uint32_t)__cvta_generic_to_shared(sBl);

    uint32_t aAh[2], aAl[2], aBh[2], aBl[2];
    #pragma unroll
    for (int mt = 0; mt < 2; mt++) {
        uint32_t off = ((wm + mt * 16 + frow) * LDS + fcol) * 2;
        aAh[mt] = bAh + off; aAl[mt] = bAl + off;
    }
    #pragma unroll
    for (int p = 0; p < 2; p++) {
        uint32_t off = ((wn + p * 16 + frow) * LDS + fcol) * 2;
        aBh[p] = bBh + off; aBl[p] = bBl + off;
    }

    float acc[2][4][4];
    #pragma unroll
    for (int mt = 0; mt < 2; mt++)
        #pragma unroll
        for (int nt = 0; nt < 4; nt++)
            #pragma unroll
            for (int j = 0; j < 4; j++) acc[mt][nt][j] = 0.f;

    float4 pa[4], pb[2];
    const int nkb = K / GBK;   // 8

    // prologue global load (kb = 0)
    {
        const float* Ap = A + (size_t)bm * K;
        const float* Bp = Bw + (size_t)bn * K;
        #pragma unroll
        for (int i = 0; i < 4; i++) {
            int s = i * 256 + tid;
            pa[i] = *reinterpret_cast<const float4*>(Ap + (size_t)(s >> 3) * K + (s & 7) * 4);
        }
        #pragma unroll
        for (int i = 0; i < 2; i++) {
            int s = i * 256 + tid;
            pb[i] = *reinterpret_cast<const float4*>(Bp + (size_t)(s >> 3) * K + (s & 7) * 4);
        }
    }
    // store to smem
    {
        #pragma unroll
        for (int i = 0; i < 4; i++) {
            int s = i * 256 + tid; int r = s >> 3, c = (s & 7) * 4;
            uint2 hi, lo; split4(pa[i], hi, lo);
            *reinterpret_cast<uint2*>(sAh + r * LDS + c) = hi;
            *reinterpret_cast<uint2*>(sAl + r * LDS + c) = lo;
        }
        #pragma unroll
        for (int i = 0; i < 2; i++) {
            int s = i * 256 + tid; int r = s >> 3, c = (s & 7) * 4;
            uint2 hi, lo; split4(pb[i], hi, lo);
            *reinterpret_cast<uint2*>(sBh + r * LDS + c) = hi;
            *reinterpret_cast<uint2*>(sBl + r * LDS + c) = lo;
        }
    }
    __syncthreads();

    for (int kb = 0; kb < nkb; kb++) {
        // prefetch next k-block to registers
        if (kb + 1 < nkb) {
            const float* Ap = A + (size_t)bm * K + (kb + 1) * GBK;
            const float* Bp = Bw + (size_t)bn * K + (kb + 1) * GBK;
            #pragma unroll
            for (int i = 0; i < 4; i++) {
                int s = i * 256 + tid;
                pa[i] = *reinterpret_cast<const float4*>(Ap + (size_t)(s >> 3) * K + (s & 7) * 4);
            }
            #pragma unroll
            for (int i = 0; i < 2; i++) {
                int s = i * 256 + tid;
                pb[i] = *reinterpret_cast<const float4*>(Bp + (size_t)(s >> 3) * K + (s & 7) * 4);
            }
        }

        // compute 2 k-steps of 16 from smem
        #pragma unroll
        for (int ks = 0; ks < 2; ks++) {
            const uint32_t koff = ks * 32;   // 16 bf16 = 32 bytes
            uint32_t ah[2][4], al[2][4], bh[2][4], bl[2][4];
            #pragma unroll
            for (int mt = 0; mt < 2; mt++) {
                ldsm_x4(aAh[mt] + koff, ah[mt][0], ah[mt][1], ah[mt][2], ah[mt][3]);
                ldsm_x4(aAl[mt] + koff, al[mt][0], al[mt][1], al[mt][2], al[mt][3]);
            }
            #pragma unroll
            for (int p = 0; p < 2; p++) {
                ldsm_x4(aBh[p] + koff, bh[p][0], bh[p][1], bh[p][2], bh[p][3]);
                ldsm_x4(aBl[p] + koff, bl[p][0], bl[p][1], bl[p][2], bl[p][3]);
            }
            #pragma unroll
            for (int mt = 0; mt < 2; mt++) {
                #pragma unroll
                for (int nt = 0; nt < 4; nt++) {
                    int p = nt >> 1, q = nt & 1;
                    uint32_t b0h = bh[p][q], b1h = bh[p][q + 2];
                    uint32_t b0l = bl[p][q], b1l = bl[p][q + 2];
                    mma_bf16(acc[mt][nt], ah[mt], b0h, b1h);   // hi*hi
                    mma_bf16(acc[mt][nt], ah[mt], b0l, b1l);   // hi*lo
                    mma_bf16(acc[mt][nt], al[mt], b0h, b1h);   // lo*hi
                }
            }
        }

        if (kb + 1 < nkb) {
            __syncthreads();
            #pragma unroll
            for (int i = 0; i < 4; i++) {
                int s = i * 256 + tid; int r = s >> 3, c = (s & 7) * 4;
                uint2 hi, lo; split4(pa[i], hi, lo);
                *reinterpret_cast<uint2*>(sAh + r * LDS + c) = hi;
                *reinterpret_cast<uint2*>(sAl + r * LDS + c) = lo;
            }
            #pragma unroll
            for (int i = 0; i < 2; i++) {
                int s = i * 256 + tid; int r = s >> 3, c = (s & 7) * 4;
                uint2 hi, lo; split4(pb[i], hi, lo);
                *reinterpret_cast<uint2*>(sBh + r * LDS + c) = hi;
                *reinterpret_cast<uint2*>(sBl + r * LDS + c) = lo;
            }
            __syncthreads();
        }
    }

    // ---- epilogue: bias + store ----
    const int er = lane >> 2;
    const int ec = (lane & 3) * 2;
    #pragma unroll
    for (int mt = 0; mt < 2; mt++) {
        #pragma unroll
        for (int nt = 0; nt < 4; nt++) {
            int row = bm + wm + mt * 16 + er;
            int col = bn + wn + nt * 8 + ec;
            float b0 = bias[col], b1 = bias[col + 1];
            float2 o0 = make_float2(acc[mt][nt][0] + b0, acc[mt][nt][1] + b1);
            float2 o1 = make_float2(acc[mt][nt][2] + b0, acc[mt][nt][3] + b1);
            *reinterpret_cast<float2*>(C + (size_t)row * N + col) = o0;
            *reinterpret_cast<float2*>(C + (size_t)(row + 8) * N + col) = o1;
        }
    }
}

// ---------------- RoPE + L2 normalize (in place on q,k of g_qkv) -----------
__global__ __launch_bounds__(256) void rope_norm_kernel()
{
    int wg   = blockIdx.x * 8 + (threadIdx.x >> 5);
    int lane = threadIdx.x & 31;
    int h = wg & 7;
    int s = (wg >> 3) & 1;
    int n = (wg >> 4) & 63;
    int b = wg >> 10;
    if (b >= B_WIN) return;

    float* row = g_qkv + ((size_t)(b * SEQ + n)) * (3 * CDIM) + s * CDIM + h * HDIM;
    float v = row[lane];

    int i = lane & 15;
    float inv_freq = powf(10000.f, -(float)i * (1.f / 16.f));
    float t   = (float)n + 0.1f;
    float ang = t * inv_freq;
    float sn = sinf(ang), c = cosf(ang);

    float partner = __shfl_xor_sync(0xffffffffu, v, 16);
    float r = (lane < 16) ? fmaf(v, c, -partner * sn)
                          : fmaf(partner, sn, v * c);

    float ss = r * r;
    #pragma unroll
    for (int o = 16; o; o >>= 1) ss += __shfl_xor_sync(0xffffffffu, ss, o);
    float nrm = fmaxf(sqrtf(ss), 1e-12f);
    row[lane] = r / nrm;
}

// ---------------- fused attention per (b, h) block --------------------------
__global__ __launch_bounds__(256) void attn_kernel(
    const float* __restrict__ mask, const float* __restrict__ logit_scale,
    float* __restrict__ out)
{
    const int h = blockIdx.x;
    const int b = blockIdx.y;
    const int w = b & (NWIN - 1);
    const int tid = threadIdx.x;

    __shared__ float qT[HDIM][SEQ + 8];
    __shared__ float kT[HDIM][SEQ + 8];
    __shared__ float vs[SEQ][HDIM + 4];
    __shared__ float S[SEQ][SEQ + 4];

    const float* base = g_qkv + (size_t)b * SEQ * (3 * CDIM) + h * HDIM;

    #pragma unroll
    for (int i = 0; i < 2; i++) {
        int slot = tid * 2 + i;
        int n  = slot >> 3;
        int c4 = (slot & 7) * 4;
        const float* rp = base + (size_t)n * (3 * CDIM) + c4;
        float4 q4 = *reinterpret_cast<const float4*>(rp);
        float4 k4 = *reinterpret_cast<const float4*>(rp + CDIM);
        float4 v4 = *reinterpret_cast<const float4*>(rp + 2 * CDIM);
        qT[c4+0][n]=q4.x; qT[c4+1][n]=q4.y; qT[c4+2][n]=q4.z; qT[c4+3][n]=q4.w;
        kT[c4+0][n]=k4.x; kT[c4+1][n]=k4.y; kT[c4+2][n]=k4.z; kT[c4+3][n]=k4.w;
        vs[n][c4+0]=v4.x; vs[n][c4+1]=v4.y; vs[n][c4+2]=v4.z; vs[n][c4+3]=v4.w;
    }
    float scale = __expf(fminf(logit_scale[h], MAX_LOGIT));
    __syncthreads();

    {
        const int r0 = (tid >> 4) << 2;
        const int c0 = (tid & 15) << 2;
        float accs[4][4];
        #pragma unroll
        for (int i=0;i<4;i++)
            #pragma unroll
            for (int j=0;j<4;j++) accs[i][j] = 0.f;

        #pragma unroll
        for (int kk = 0; kk < HDIM; kk++) {
            float4 qv = *reinterpret_cast<float4*>(&qT[kk][r0]);
            float4 kv = *reinterpret_cast<float4*>(&kT[kk][c0]);
            float ra[4] = {qv.x, qv.y, qv.z, qv.w};
            float rb[4] = {kv.x, kv.y, kv.z, kv.w};
            #pragma unroll
            for (int i=0;i<4;i++)
                #pragma unroll
                for (int j=0;j<4;j++)
                    accs[i][j] = fmaf(ra[i], rb[j], accs[i][j]);
        }
        const float* mrow = mask + (size_t)w * SEQ * SEQ;
        #pragma unroll
        for (int i=0;i<4;i++)
            #pragma unroll
            for (int j=0;j<4;j++)
                S[r0+i][c0+j] = fmaf(accs[i][j], scale, mrow[(r0+i)*SEQ + c0+j]);
    }
    __syncthreads();

    {
        const int row = tid >> 2;
        const int q16 = (tid & 3) * 16;
        float mx = -1e30f;
        #pragma unroll
        for (int j = 0; j < 16; j++) mx = fmaxf(mx, S[row][q16 + j]);
        mx = fmaxf(mx, __shfl_xor_sync(0xffffffffu, mx, 1));
        mx = fmaxf(mx, __shfl_xor_sync(0xffffffffu, mx, 2));
        float e[16]; float sum = 0.f;
        #pragma unroll
        for (int j = 0; j < 16; j++) { e[j] = __expf(S[row][q16 + j] - mx); sum += e[j]; }
        sum += __shfl_xor_sync(0xffffffffu, sum, 1);
        sum += __shfl_xor_sync(0xffffffffu, sum, 2);
        float inv = __frcp_rn(sum);
        #pragma unroll
        for (int j = 0; j < 16; j++) S[row][q16 + j] = e[j] * inv;
    }
    __syncthreads();

    {
        const int r0 = (tid >> 3) << 1;
        const int d0 = (tid & 7) << 2;
        float o0[4] = {0,0,0,0}, o1[4] = {0,0,0,0};
        #pragma unroll
        for (int c = 0; c < SEQ; c++) {
            float p0 = S[r0][c];
            float p1 = S[r0 + 1][c];
            float4 vv = *reinterpret_cast<float4*>(&vs[c][d0]);
            o0[0] = fmaf(p0, vv.x, o0[0]); o0[1] = fmaf(p0, vv.y, o0[1]);
            o0[2] = fmaf(p0, vv.z, o0[2]); o0[3] = fmaf(p0, vv.w, o0[3]);
            o1[0] = fmaf(p1, vv.x, o1[0]); o1[1] = fmaf(p1, vv.y, o1[1]);
            o1[2] = fmaf(p1, vv.z, o1[2]); o1[3] = fmaf(p1, vv.w, o1[3]);
        }
        float* orow = out + ((size_t)(b * SEQ + r0)) * CDIM + h * HDIM + d0;
        *reinterpret_cast<float4*>(orow)        = make_float4(o0[0], o0[1], o0[2], o0[3]);
        *reinterpret_cast<float4*>(orow + CDIM) = make_float4(o1[0], o1[1], o1[2], o1[3]);
    }
}

// ---------------- launch ----------------------------------------------------
extern "C" void kernel_launch(void* const* d_in, const int* in_sizes, int n_in,
                              void* d_out, int out_size)
{
    const float* x           = (const float*)d_in[0];
    const float* mask        = (const float*)d_in[1];
    const float* qkv_w       = (const float*)d_in[2];
    const float* qkv_b       = (const float*)d_in[3];
    const float* proj_w      = (const float*)d_in[4];
    const float* proj_b      = (const float*)d_in[5];
    const float* logit_scale = (const float*)d_in[6];
    float* out = (float*)d_out;

    float* qkv_buf;
    float* attn_buf;
    cudaGetSymbolAddress((void**)&qkv_buf, g_qkv);
    cudaGetSymbolAddress((void**)&attn_buf, g_attn);

    const int M = B_WIN * SEQ;          // 262144

    // 1) QKV GEMM (tensor cores, bf16 split)
    {
        dim3 grid(3 * CDIM / GBN, M / GBM);   // (12, 2048)
        gemm_bf16_split<<<grid, 256>>>(x, qkv_w, qkv_b, qkv_buf, M, 3 * CDIM, CDIM);
    }
    // 2) RoPE + L2 norm on q,k
    {
        int total_warps = B_WIN * SEQ * 2 * NHEAD;
        rope_norm_kernel<<<total_warps / 8, 256>>>();
    }
    // 3) fused attention
    {
        dim3 grid(NHEAD, B_WIN);
        attn_kernel<<<grid, 256>>>(mask, logit_scale, attn_buf);
    }
    // 4) proj GEMM (tensor cores, bf16 split)
    {
        dim3 grid(CDIM / GBN, M / GBM);       // (4, 2048)
        gemm_bf16_split<<<grid, 256>>>(attn_buf, proj_w, proj_b, out, M, CDIM, CDIM);
    }
}

// round 5
// speedup vs baseline: 2.2549x; 1.4176x over previous
#include <cuda_runtime.h>
#include <cuda_bf16.h>
#include <cstdint>

// Problem constants
#define B_WIN   4096
#define SEQ     64
#define CDIM    256
#define NHEAD   8
#define HDIM    32
#define NWIN    64
#define MAX_LOGIT 4.6051701859880913680f  // log(100)

// ---------------- scratch (device globals; no runtime allocation) ----------
__device__ float g_qkv[(size_t)B_WIN * SEQ * 3 * CDIM];   // [b*64+n][768]
__device__ float g_attn[(size_t)B_WIN * SEQ * CDIM];      // [b*64+n][256]

// ================= common mma helpers ======================================
__device__ __forceinline__ uint32_t pack_bf2(float a, float b) {
    __nv_bfloat162 t = __floats2bfloat162_rn(a, b);
    return *reinterpret_cast<uint32_t*>(&t);
}

__device__ __forceinline__ void ldsm_x4(uint32_t addr, uint32_t& r0, uint32_t& r1,
                                        uint32_t& r2, uint32_t& r3) {
    asm volatile("ldmatrix.sync.aligned.m8n8.x4.shared.b16 {%0,%1,%2,%3}, [%4];"
                 : "=r"(r0), "=r"(r1), "=r"(r2), "=r"(r3) : "r"(addr));
}

__device__ __forceinline__ void mma_bf16(float* c, const uint32_t* a,
                                         uint32_t b0, uint32_t b1) {
    asm volatile(
        "mma.sync.aligned.m16n8k16.row.col.f32.bf16.bf16.f32 "
        "{%0,%1,%2,%3}, {%4,%5,%6,%7}, {%8,%9}, {%0,%1,%2,%3};"
        : "+f"(c[0]), "+f"(c[1]), "+f"(c[2]), "+f"(c[3])
        : "r"(a[0]), "r"(a[1]), "r"(a[2]), "r"(a[3]), "r"(b0), "r"(b1));
}

// split float4 into hi/lo bf16x4 packed as uint2
__device__ __forceinline__ void split4(float4 v, uint2& hi, uint2& lo) {
    float vv[4] = {v.x, v.y, v.z, v.w};
    float hf[4], lf[4];
    #pragma unroll
    for (int j = 0; j < 4; j++) {
        __nv_bfloat16 h = __float2bfloat16_rn(vv[j]);
        hf[j] = __bfloat162float(h);
        lf[j] = vv[j] - hf[j];
    }
    hi.x = pack_bf2(hf[0], hf[1]); hi.y = pack_bf2(hf[2], hf[3]);
    lo.x = pack_bf2(lf[0], lf[1]); lo.y = pack_bf2(lf[2], lf[3]);
}

// ================= bf16-split tensor-core GEMM (unchanged from R3) =========
#define GBM 128
#define GBN 64
#define GBK 32
#define LDS 40

__global__ __launch_bounds__(256, 2) void gemm_bf16_split(
    const float* __restrict__ A, const float* __restrict__ Bw,
    const float* __restrict__ bias, float* __restrict__ C,
    int M, int N, int K)
{
    __shared__ __align__(16) __nv_bfloat16 sAh[GBM * LDS];
    __shared__ __align__(16) __nv_bfloat16 sAl[GBM * LDS];
    __shared__ __align__(16) __nv_bfloat16 sBh[GBN * LDS];
    __shared__ __align__(16) __nv_bfloat16 sBl[GBN * LDS];

    const int tid  = threadIdx.x;
    const int lane = tid & 31;
    const int wid  = tid >> 5;
    const int bm   = blockIdx.y * GBM;
    const int bn   = blockIdx.x * GBN;
    const int wm   = (wid & 3) * 32;
    const int wn   = (wid >> 2) * 32;

    const int lr   = lane & 7;
    const int seg  = lane >> 3;
    const int frow = lr + (seg & 1) * 8;
    const int fcol = (seg >> 1) * 8;

    const uint32_t bAh = (uint32_t)__cvta_generic_to_shared(sAh);
    const uint32_t bAl = (uint32_t)__cvta_generic_to_shared(sAl);
    const uint32_t bBh = (uint32_t)__cvta_generic_to_shared(sBh);
    const uint32_t bBl = (uint32_t)__cvta_generic_to_shared(sBl);

    uint32_t aAh[2], aAl[2], aBh[2], aBl[2];
    #pragma unroll
    for (int mt = 0; mt < 2; mt++) {
        uint32_t off = ((wm + mt * 16 + frow) * LDS + fcol) * 2;
        aAh[mt] = bAh + off; aAl[mt] = bAl + off;
    }
    #pragma unroll
    for (int p = 0; p < 2; p++) {
        uint32_t off = ((wn + p * 16 + frow) * LDS + fcol) * 2;
        aBh[p] = bBh + off; aBl[p] = bBl + off;
    }

    float acc[2][4][4];
    #pragma unroll
    for (int mt = 0; mt < 2; mt++)
        #pragma unroll
        for (int nt = 0; nt < 4; nt++)
            #pragma unroll
            for (int j = 0; j < 4; j++) acc[mt][nt][j] = 0.f;

    float4 pa[4], pb[2];
    const int nkb = K / GBK;

    {
        const float* Ap = A + (size_t)bm * K;
        const float* Bp = Bw + (size_t)bn * K;
        #pragma unroll
        for (int i = 0; i < 4; i++) {
            int s = i * 256 + tid;
            pa[i] = *reinterpret_cast<const float4*>(Ap + (size_t)(s >> 3) * K + (s & 7) * 4);
        }
        #pragma unroll
        for (int i = 0; i < 2; i++) {
            int s = i * 256 + tid;
            pb[i] = *reinterpret_cast<const float4*>(Bp + (size_t)(s >> 3) * K + (s & 7) * 4);
        }
    }
    {
        #pragma unroll
        for (int i = 0; i < 4; i++) {
            int s = i * 256 + tid; int r = s >> 3, c = (s & 7) * 4;
            uint2 hi, lo; split4(pa[i], hi, lo);
            *reinterpret_cast<uint2*>(sAh + r * LDS + c) = hi;
            *reinterpret_cast<uint2*>(sAl + r * LDS + c) = lo;
        }
        #pragma unroll
        for (int i = 0; i < 2; i++) {
            int s = i * 256 + tid; int r = s >> 3, c = (s & 7) * 4;
            uint2 hi, lo; split4(pb[i], hi, lo);
            *reinterpret_cast<uint2*>(sBh + r * LDS + c) = hi;
            *reinterpret_cast<uint2*>(sBl + r * LDS + c) = lo;
        }
    }
    __syncthreads();

    for (int kb = 0; kb < nkb; kb++) {
        if (kb + 1 < nkb) {
            const float* Ap = A + (size_t)bm * K + (kb + 1) * GBK;
            const float* Bp = Bw + (size_t)bn * K + (kb + 1) * GBK;
            #pragma unroll
            for (int i = 0; i < 4; i++) {
                int s = i * 256 + tid;
                pa[i] = *reinterpret_cast<const float4*>(Ap + (size_t)(s >> 3) * K + (s & 7) * 4);
            }
            #pragma unroll
            for (int i = 0; i < 2; i++) {
                int s = i * 256 + tid;
                pb[i] = *reinterpret_cast<const float4*>(Bp + (size_t)(s >> 3) * K + (s & 7) * 4);
            }
        }

        #pragma unroll
        for (int ks = 0; ks < 2; ks++) {
            const uint32_t koff = ks * 32;
            uint32_t ah[2][4], al[2][4], bh[2][4], bl[2][4];
            #pragma unroll
            for (int mt = 0; mt < 2; mt++) {
                ldsm_x4(aAh[mt] + koff, ah[mt][0], ah[mt][1], ah[mt][2], ah[mt][3]);
                ldsm_x4(aAl[mt] + koff, al[mt][0], al[mt][1], al[mt][2], al[mt][3]);
            }
            #pragma unroll
            for (int p = 0; p < 2; p++) {
                ldsm_x4(aBh[p] + koff, bh[p][0], bh[p][1], bh[p][2], bh[p][3]);
                ldsm_x4(aBl[p] + koff, bl[p][0], bl[p][1], bl[p][2], bl[p][3]);
            }
            #pragma unroll
            for (int mt = 0; mt < 2; mt++) {
                #pragma unroll
                for (int nt = 0; nt < 4; nt++) {
                    int p = nt >> 1, q = nt & 1;
                    uint32_t b0h = bh[p][q], b1h = bh[p][q + 2];
                    uint32_t b0l = bl[p][q], b1l = bl[p][q + 2];
                    mma_bf16(acc[mt][nt], ah[mt], b0h, b1h);
                    mma_bf16(acc[mt][nt], ah[mt], b0l, b1l);
                    mma_bf16(acc[mt][nt], al[mt], b0h, b1h);
                }
            }
        }

        if (kb + 1 < nkb) {
            __syncthreads();
            #pragma unroll
            for (int i = 0; i < 4; i++) {
                int s = i * 256 + tid; int r = s >> 3, c = (s & 7) * 4;
                uint2 hi, lo; split4(pa[i], hi, lo);
                *reinterpret_cast<uint2*>(sAh + r * LDS + c) = hi;
                *reinterpret_cast<uint2*>(sAl + r * LDS + c) = lo;
            }
            #pragma unroll
            for (int i = 0; i < 2; i++) {
                int s = i * 256 + tid; int r = s >> 3, c = (s & 7) * 4;
                uint2 hi, lo; split4(pb[i], hi, lo);
                *reinterpret_cast<uint2*>(sBh + r * LDS + c) = hi;
                *reinterpret_cast<uint2*>(sBl + r * LDS + c) = lo;
            }
            __syncthreads();
        }
    }

    const int er = lane >> 2;
    const int ec = (lane & 3) * 2;
    #pragma unroll
    for (int mt = 0; mt < 2; mt++) {
        #pragma unroll
        for (int nt = 0; nt < 4; nt++) {
            int row = bm + wm + mt * 16 + er;
            int col = bn + wn + nt * 8 + ec;
            float b0 = bias[col], b1 = bias[col + 1];
            float2 o0 = make_float2(acc[mt][nt][0] + b0, acc[mt][nt][1] + b1);
            float2 o1 = make_float2(acc[mt][nt][2] + b0, acc[mt][nt][3] + b1);
            *reinterpret_cast<float2*>(C + (size_t)row * N + col) = o0;
            *reinterpret_cast<float2*>(C + (size_t)(row + 8) * N + col) = o1;
        }
    }
}

// ============ fused RoPE + norm + tensor-core attention per (b,h) ==========
// 128 threads = 4 warps; warp w computes S rows [16w, 16w+16).
#define VLD 72   // V^T row length (64 + 8 pad)

__global__ __launch_bounds__(128) void attn_mma_kernel(
    const float* __restrict__ mask, const float* __restrict__ logit_scale,
    float* __restrict__ out)
{
    const int h = blockIdx.x;
    const int b = blockIdx.y;
    const int w = b & (NWIN - 1);
    const int tid  = threadIdx.x;
    const int lane = tid & 31;
    const int wid  = tid >> 5;

    __shared__ __align__(16) __nv_bfloat16 qh[SEQ * LDS];
    __shared__ __align__(16) __nv_bfloat16 ql[SEQ * LDS];
    __shared__ __align__(16) __nv_bfloat16 kh[SEQ * LDS];
    __shared__ __align__(16) __nv_bfloat16 kl[SEQ * LDS];
    __shared__ __align__(16) __nv_bfloat16 vth[HDIM * VLD];  // V^T hi
    __shared__ __align__(16) __nv_bfloat16 vtl[HDIM * VLD];  // V^T lo
    __shared__ float msk[SEQ][SEQ + 4];

    const float* base = g_qkv + (size_t)b * SEQ * (3 * CDIM) + h * HDIM;

    // ---- load q or k row, RoPE + normalize, split to bf16 hi/lo ----
    {
        const int s = tid >> 6;        // 0 = q, 1 = k
        const int n = tid & 63;
        const float* rp = base + (size_t)n * (3 * CDIM) + s * CDIM;
        float v[32];
        #pragma unroll
        for (int i = 0; i < 8; i++) {
            float4 t = *reinterpret_cast<const float4*>(rp + i * 4);
            v[i*4+0]=t.x; v[i*4+1]=t.y; v[i*4+2]=t.z; v[i*4+3]=t.w;
        }
        float r[32];
        const float tp = (float)n + 0.1f;
        #pragma unroll
        for (int i = 0; i < 16; i++) {
            float inv_freq = exp2f(-(float)i * 0.8304820237218405f); // log2(1e4)/16
            float ang = tp * inv_freq;
            float sn = sinf(ang), cs = cosf(ang);
            r[i]      = v[i] * cs - v[i + 16] * sn;
            r[i + 16] = v[i] * sn + v[i + 16] * cs;
        }
        float ss = 0.f;
        #pragma unroll
        for (int i = 0; i < 32; i++) ss += r[i] * r[i];
        float inv = 1.0f / fmaxf(sqrtf(ss), 1e-12f);
        __nv_bfloat16* dh = (s == 0 ? qh : kh) + n * LDS;
        __nv_bfloat16* dl = (s == 0 ? ql : kl) + n * LDS;
        #pragma unroll
        for (int i = 0; i < 32; i += 2) {
            float a0 = r[i] * inv, a1 = r[i + 1] * inv;
            __nv_bfloat162 hi2 = __floats2bfloat162_rn(a0, a1);
            float h0 = __bfloat162float(__low2bfloat16(hi2));
            float h1 = __bfloat162float(__high2bfloat16(hi2));
            *reinterpret_cast<uint32_t*>(dh + i) = *reinterpret_cast<uint32_t*>(&hi2);
            *reinterpret_cast<uint32_t*>(dl + i) = pack_bf2(a0 - h0, a1 - h1);
        }
    }
    // ---- load V transposed, split hi/lo ----
    {
        const int n = tid & 63;
        const int dh0 = (tid >> 6) * 16;
        const float* rp = base + (size_t)n * (3 * CDIM) + 2 * CDIM + dh0;
        #pragma unroll
        for (int i = 0; i < 4; i++) {
            float4 t = *reinterpret_cast<const float4*>(rp + i * 4);
            float vv[4] = {t.x, t.y, t.z, t.w};
            #pragma unroll
            for (int j = 0; j < 4; j++) {
                int d = dh0 + i * 4 + j;
                __nv_bfloat16 hb = __float2bfloat16_rn(vv[j]);
                vth[d * VLD + n] = hb;
                vtl[d * VLD + n] = __float2bfloat16_rn(vv[j] - __bfloat162float(hb));
            }
        }
    }
    // ---- load mask tile ----
    {
        const float* mp = mask + (size_t)w * SEQ * SEQ;
        #pragma unroll
        for (int i = 0; i < 8; i++) {
            int s = i * 128 + tid;
            int r = s >> 4, c4 = (s & 15) * 4;
            *reinterpret_cast<float4*>(&msk[r][c4]) =
                *reinterpret_cast<const float4*>(mp + r * SEQ + c4);
        }
    }
    const float scale = expf(fminf(logit_scale[h], MAX_LOGIT));
    __syncthreads();

    // ---- fragment addressing ----
    const int lr   = lane & 7;
    const int seg  = lane >> 3;
    const int frow = lr + (seg & 1) * 8;
    const int fcol = (seg >> 1) * 8;
    const int wm   = wid * 16;

    const uint32_t bQh = (uint32_t)__cvta_generic_to_shared(qh);
    const uint32_t bQl = (uint32_t)__cvta_generic_to_shared(ql);
    const uint32_t bKh = (uint32_t)__cvta_generic_to_shared(kh);
    const uint32_t bKl = (uint32_t)__cvta_generic_to_shared(kl);
    const uint32_t bVh = (uint32_t)__cvta_generic_to_shared(vth);
    const uint32_t bVl = (uint32_t)__cvta_generic_to_shared(vtl);

    const uint32_t aQ = ((wm + frow) * LDS + fcol) * 2;

    // ---- S = qn . kn^T  (3-pass split), acc[j] = cols 8j..8j+7 ----
    float acc[8][4];
    #pragma unroll
    for (int j = 0; j < 8; j++)
        #pragma unroll
        for (int u = 0; u < 4; u++) acc[j][u] = 0.f;

    #pragma unroll
    for (int ks = 0; ks < 2; ks++) {
        const uint32_t koff = ks * 32;
        uint32_t ah[4], al[4];
        ldsm_x4(bQh + aQ + koff, ah[0], ah[1], ah[2], ah[3]);
        ldsm_x4(bQl + aQ + koff, al[0], al[1], al[2], al[3]);
        uint32_t bhf[4][4], blf[4][4];
        #pragma unroll
        for (int p = 0; p < 4; p++) {
            uint32_t off = ((p * 16 + frow) * LDS + fcol) * 2 + koff;
            ldsm_x4(bKh + off, bhf[p][0], bhf[p][1], bhf[p][2], bhf[p][3]);
            ldsm_x4(bKl + off, blf[p][0], blf[p][1], blf[p][2], blf[p][3]);
        }
        #pragma unroll
        for (int j = 0; j < 8; j++) {
            int p = j >> 1, q = j & 1;
            mma_bf16(acc[j], ah, bhf[p][q], bhf[p][q + 2]);
            mma_bf16(acc[j], ah, blf[p][q], blf[p][q + 2]);
            mma_bf16(acc[j], al, bhf[p][q], bhf[p][q + 2]);
        }
    }

    // ---- scale + mask + softmax entirely in registers ----
    {
        const int r0 = wm + (lane >> 2);
        const int c0 = (lane & 3) * 2;
        float m0 = -1e30f, m1 = -1e30f;
        #pragma unroll
        for (int j = 0; j < 8; j++) {
            acc[j][0] = fmaf(acc[j][0], scale, msk[r0][8*j + c0]);
            acc[j][1] = fmaf(acc[j][1], scale, msk[r0][8*j + c0 + 1]);
            acc[j][2] = fmaf(acc[j][2], scale, msk[r0 + 8][8*j + c0]);
            acc[j][3] = fmaf(acc[j][3], scale, msk[r0 + 8][8*j + c0 + 1]);
            m0 = fmaxf(m0, fmaxf(acc[j][0], acc[j][1]));
            m1 = fmaxf(m1, fmaxf(acc[j][2], acc[j][3]));
        }
        m0 = fmaxf(m0, __shfl_xor_sync(0xffffffffu, m0, 1));
        m0 = fmaxf(m0, __shfl_xor_sync(0xffffffffu, m0, 2));
        m1 = fmaxf(m1, __shfl_xor_sync(0xffffffffu, m1, 1));
        m1 = fmaxf(m1, __shfl_xor_sync(0xffffffffu, m1, 2));
        float s0 = 0.f, s1 = 0.f;
        #pragma unroll
        for (int j = 0; j < 8; j++) {
            acc[j][0] = __expf(acc[j][0] - m0);
            acc[j][1] = __expf(acc[j][1] - m0);
            acc[j][2] = __expf(acc[j][2] - m1);
            acc[j][3] = __expf(acc[j][3] - m1);
            s0 += acc[j][0] + acc[j][1];
            s1 += acc[j][2] + acc[j][3];
        }
        s0 += __shfl_xor_sync(0xffffffffu, s0, 1);
        s0 += __shfl_xor_sync(0xffffffffu, s0, 2);
        s1 += __shfl_xor_sync(0xffffffffu, s1, 1);
        s1 += __shfl_xor_sync(0xffffffffu, s1, 2);
        float i0 = 1.0f / s0, i1 = 1.0f / s1;
        #pragma unroll
        for (int j = 0; j < 8; j++) {
            acc[j][0] *= i0; acc[j][1] *= i0;
            acc[j][2] *= i1; acc[j][3] *= i1;
        }
    }

    // ---- out = P . V : P A-frags built from registers, V^T from smem ----
    float acco[4][4];
    #pragma unroll
    for (int j = 0; j < 4; j++)
        #pragma unroll
        for (int u = 0; u < 4; u++) acco[j][u] = 0.f;

    #pragma unroll
    for (int ks = 0; ks < 4; ks++) {
        // A fragments from P registers (tiles 2ks, 2ks+1)
        uint32_t pah[4], pal[4];
        {
            const float* t0 = acc[2 * ks];
            const float* t1 = acc[2 * ks + 1];
            float h;
            __nv_bfloat162 x;
            x = __floats2bfloat162_rn(t0[0], t0[1]);
            pah[0] = *reinterpret_cast<uint32_t*>(&x);
            h = __bfloat162float(__low2bfloat16(x));
            float l0 = t0[0] - h;
            h = __bfloat162float(__high2bfloat16(x));
            pal[0] = pack_bf2(l0, t0[1] - h);

            x = __floats2bfloat162_rn(t0[2], t0[3]);
            pah[1] = *reinterpret_cast<uint32_t*>(&x);
            h = __bfloat162float(__low2bfloat16(x));
            l0 = t0[2] - h;
            h = __bfloat162float(__high2bfloat16(x));
            pal[1] = pack_bf2(l0, t0[3] - h);

            x = __floats2bfloat162_rn(t1[0], t1[1]);
            pah[2] = *reinterpret_cast<uint32_t*>(&x);
            h = __bfloat162float(__low2bfloat16(x));
            l0 = t1[0] - h;
            h = __bfloat162float(__high2bfloat16(x));
            pal[2] = pack_bf2(l0, t1[1] - h);

            x = __floats2bfloat162_rn(t1[2], t1[3]);
            pah[3] = *reinterpret_cast<uint32_t*>(&x);
            h = __bfloat162float(__low2bfloat16(x));
            l0 = t1[2] - h;
            h = __bfloat162float(__high2bfloat16(x));
            pal[3] = pack_bf2(l0, t1[3] - h);
        }
        const uint32_t koff = ks * 32;
        uint32_t vh[2][4], vl[2][4];
        #pragma unroll
        for (int p = 0; p < 2; p++) {
            uint32_t off = ((p * 16 + frow) * VLD + fcol) * 2 + koff;
            ldsm_x4(bVh + off, vh[p][0], vh[p][1], vh[p][2], vh[p][3]);
            ldsm_x4(bVl + off, vl[p][0], vl[p][1], vl[p][2], vl[p][3]);
        }
        #pragma unroll
        for (int j = 0; j < 4; j++) {
            int p = j >> 1, q = j & 1;
            mma_bf16(acco[j], pah, vh[p][q], vh[p][q + 2]);
            mma_bf16(acco[j], pah, vl[p][q], vl[p][q + 2]);
            mma_bf16(acco[j], pal, vh[p][q], vh[p][q + 2]);
        }
    }

    // ---- store out[b*64 + row][h*32 + d] ----
    {
        const int er = lane >> 2;
        const int ec = (lane & 3) * 2;
        float* orow = out + ((size_t)(b * SEQ + wm + er)) * CDIM + h * HDIM + ec;
        #pragma unroll
        for (int j = 0; j < 4; j++) {
            *reinterpret_cast<float2*>(orow + 8 * j) =
                make_float2(acco[j][0], acco[j][1]);
            *reinterpret_cast<float2*>(orow + 8 * CDIM + 8 * j) =
                make_float2(acco[j][2], acco[j][3]);
        }
    }
}

// ---------------- launch ----------------------------------------------------
extern "C" void kernel_launch(void* const* d_in, const int* in_sizes, int n_in,
                              void* d_out, int out_size)
{
    const float* x           = (const float*)d_in[0];
    const float* mask        = (const float*)d_in[1];
    const float* qkv_w       = (const float*)d_in[2];
    const float* qkv_b       = (const float*)d_in[3];
    const float* proj_w      = (const float*)d_in[4];
    const float* proj_b      = (const float*)d_in[5];
    const float* logit_scale = (const float*)d_in[6];
    float* out = (float*)d_out;

    float* qkv_buf;
    float* attn_buf;
    cudaGetSymbolAddress((void**)&qkv_buf, g_qkv);
    cudaGetSymbolAddress((void**)&attn_buf, g_attn);

    const int M = B_WIN * SEQ;          // 262144

    // 1) QKV GEMM (tensor cores, bf16 split)
    {
        dim3 grid(3 * CDIM / GBN, M / GBM);   // (12, 2048)
        gemm_bf16_split<<<grid, 256>>>(x, qkv_w, qkv_b, qkv_buf, M, 3 * CDIM, CDIM);
    }
    // 2) fused RoPE + norm + attention (tensor cores)
    {
        dim3 grid(NHEAD, B_WIN);
        attn_mma_kernel<<<grid, 128>>>(mask, logit_scale, attn_buf);
    }
    // 3) proj GEMM (tensor cores, bf16 split)
    {
        dim3 grid(CDIM / GBN, M / GBM);       // (4, 2048)
        gemm_bf16_split<<<grid, 256>>>(attn_buf, proj_w, proj_b, out, M, CDIM, CDIM);
    }
}